// round 14
// baseline (speedup 1.0000x reference)
#include <cuda_runtime.h>
#include <cuda_fp16.h>

#define NMAX 50000
#define EMAX 800000
#define HIDDIM 64
#define LN_EPS 1e-5f
#define SCAN_CHUNK 4096

// ---------------- scratch (device globals; no allocation allowed) ----------------
// Self-cleaning counters: zero at module load; scan_kernel zeroes srcdeg/cursor
// (own chunk), scatter_kernel zeroes rowcnt. Deterministic across graph replays.
// fp16 feature arrays are PRE-SCALED by dinv: g_Hh = dinv*H, g_T1h = dinv*T1,
// so CSR entries need no weight (w*H[s] = -dinv[d] * (dinv[s]*H[s])).
__device__ __align__(16) int   g_srcdeg[NMAX];
__device__ __align__(16) int   g_rowcnt[NMAX];
__device__ __align__(16) int   g_cursor[NMAX];
__device__ __align__(16) int   g_rowptr[NMAX + 1];
__device__ __align__(16) float g_dinv[NMAX];
__device__ __align__(16) int   g_csrs[EMAX];             // src index only, grouped by dst
__device__ __align__(16) float g_H [NMAX * HIDDIM];
__device__ __align__(16) float g_T1[NMAX * HIDDIM];
__device__ __align__(16) float g_T2[NMAX * HIDDIM];
__device__ __align__(16) __half2 g_Hh [NMAX * 32];       // fp16 dinv*H  (spmm gather)
__device__ __align__(16) __half2 g_T1h[NMAX * 32];       // fp16 dinv*T1 (spmm gather)
__device__ __align__(16) float g_A [3 * 3 * HIDDIM * HIDDIM];  // folded weights per layer

// ---------------- f32x2 packed-FMA helpers (sm_100+ PTX) ----------------
__device__ __forceinline__ unsigned long long pack2(float a, float b) {
    unsigned long long r;
    asm("mov.b64 %0, {%1, %2};" : "=l"(r) : "f"(a), "f"(b));
    return r;
}
__device__ __forceinline__ unsigned long long ffma2(unsigned long long a,
                                                    unsigned long long b,
                                                    unsigned long long c) {
    unsigned long long d;
    asm("fma.rn.f32x2 %0, %1, %2, %3;" : "=l"(d) : "l"(a), "l"(b), "l"(c));
    return d;
}
__device__ __forceinline__ float2 unpack2(unsigned long long v) {
    float2 f;
    asm("mov.b64 {%0, %1}, %2;" : "=f"(f.x), "=f"(f.y) : "l"(v));
    return f;
}

// pack 8 floats (scaled by s) -> uint4 of 8 halves
__device__ __forceinline__ uint4 pack_half8s(const float* o, float s) {
    union { __half2 h[4]; uint4 u; } p;
    p.h[0] = __float22half2_rn(make_float2(o[0] * s, o[1] * s));
    p.h[1] = __float22half2_rn(make_float2(o[2] * s, o[3] * s));
    p.h[2] = __float22half2_rn(make_float2(o[4] * s, o[5] * s));
    p.h[3] = __float22half2_rn(make_float2(o[6] * s, o[7] * s));
    return p.u;
}

// ---------------- fused input GEMM + weight folding ----------------
// NOTE: runs AFTER scan (needs dinv for the pre-scaled g_Hh store).
__global__ __launch_bounds__(256) void ingemm_prep_kernel(const float* __restrict__ x,
                                                          const float* __restrict__ Win,
                                                          const float* __restrict__ bin,
                                                          const float* __restrict__ chW,
                                                          int gemm_blocks, int n) {
    if (blockIdx.x >= gemm_blocks) {
        int idx = (blockIdx.x - gemm_blocks) * 256 + threadIdx.x;
        if (idx < 3 * 4096) {
            int i = idx >> 12, r = idx & 4095;
            const float* Wi = chW + i * 3 * 4096;
            float w0 = Wi[r], w1 = Wi[4096 + r], w2 = Wi[8192 + r];
            float* Ai = g_A + i * 3 * 4096;
            Ai[r]        = w0 - w2;
            Ai[4096 + r] = w1;
            Ai[8192 + r] = 2.0f * w2;
        }
        return;
    }
    __shared__ float sW[16 * 64];
    __shared__ float xt[16 * 33];
    __shared__ float so[32 * 65];
    int t = threadIdx.x, lane = t & 31, wg = t >> 5;
    int row0 = blockIdx.x * 32;
    for (int idx = t; idx < 1024; idx += 256) sW[idx] = Win[idx];
    for (int idx = t; idx < 512; idx += 256) {
        int r = idx >> 4, k = idx & 15;
        int row = row0 + r;
        xt[k * 33 + r] = (row < n) ? x[row * 16 + k] : 0.0f;
    }
    __syncthreads();
    float acc[8] = {0, 0, 0, 0, 0, 0, 0, 0};
    #pragma unroll
    for (int k = 0; k < 16; k++) {
        float xv = xt[k * 33 + lane];
        float4 w0 = *(const float4*)&sW[k * 64 + wg * 8];
        float4 w1 = *(const float4*)&sW[k * 64 + wg * 8 + 4];
        acc[0] += xv * w0.x; acc[1] += xv * w0.y; acc[2] += xv * w0.z; acc[3] += xv * w0.w;
        acc[4] += xv * w1.x; acc[5] += xv * w1.y; acc[6] += xv * w1.z; acc[7] += xv * w1.w;
    }
    #pragma unroll
    for (int u = 0; u < 8; u++) {
        int j = wg * 8 + u;
        so[lane * 65 + j] = acc[u] + bin[j];
    }
    __syncthreads();
    int r = t >> 3, c = (t & 7) * 8;
    int row = row0 + r;
    if (row < n) {
        float v[8];
        #pragma unroll
        for (int u = 0; u < 8; u++) v[u] = so[r * 65 + c + u];
        *(float4*)(g_H + row * 64 + c)     = make_float4(v[0], v[1], v[2], v[3]);
        *(float4*)(g_H + row * 64 + c + 4) = make_float4(v[4], v[5], v[6], v[7]);
        float dv = g_dinv[row];
        *(uint4*)(g_Hh + row * 32 + c / 2) = pack_half8s(v, dv);
    }
}

// scalar, 1 edge/thread (measured fastest across rounds)
__global__ void count_kernel(const int* __restrict__ src, const int* __restrict__ dst, int e) {
    int i = blockIdx.x * blockDim.x + threadIdx.x;
    if (i < e) {
        atomicAdd(&g_srcdeg[src[i]], 1);
        atomicAdd(&g_rowcnt[dst[i]], 1);
    }
}

// ---------------- communication-free scan: rowcnt -> rowptr (exclusive) --------
__global__ __launch_bounds__(1024) void scan_kernel(int n) {
#if __CUDA_ARCH__ >= 900
    cudaGridDependencySynchronize();
#endif
    __shared__ int warp_tot[32];
    __shared__ int warp_sum[32];
    __shared__ int s_prev;
    int b = blockIdx.x, t = threadIdx.x, lane = t & 31, wid = t >> 5;
    int i = b * SCAN_CHUNK + t * 4;
    const int4 zero4 = make_int4(0, 0, 0, 0);

    int4 v = zero4;
    bool act = (i + 3) < n;
    if (act) {
        v = *(const int4*)(g_rowcnt + i);
        int4 dg = *(const int4*)(g_srcdeg + i);
        *(int4*)(g_srcdeg + i) = zero4;
        *(int4*)(g_cursor + i) = zero4;
        float4 dv;
        dv.x = (dg.x > 0) ? rsqrtf((float)dg.x) : 0.0f;
        dv.y = (dg.y > 0) ? rsqrtf((float)dg.y) : 0.0f;
        dv.z = (dg.z > 0) ? rsqrtf((float)dg.z) : 0.0f;
        dv.w = (dg.w > 0) ? rsqrtf((float)dg.w) : 0.0f;
        *(float4*)(g_dinv + i) = dv;
    } else {
        for (int q = 0; q < 4; q++) {
            int ii = i + q;
            if (ii < n) {
                ((int*)&v)[q] = g_rowcnt[ii];
                int d = g_srcdeg[ii]; g_srcdeg[ii] = 0;
                g_cursor[ii] = 0;
                g_dinv[ii] = (d > 0) ? rsqrtf((float)d) : 0.0f;
            }
        }
    }

    int psum = 0;
    int m = b * SCAN_CHUNK;
    for (int j = t * 4; j < m; j += 4096) {
        int4 c = *(const int4*)(g_rowcnt + j);
        psum += c.x + c.y + c.z + c.w;
    }
    #pragma unroll
    for (int off = 16; off > 0; off >>= 1)
        psum += __shfl_xor_sync(0xffffffffu, psum, off);
    if (lane == 0) warp_sum[wid] = psum;

    int tsum = v.x + v.y + v.z + v.w;
    int x = tsum;
    #pragma unroll
    for (int off = 1; off < 32; off <<= 1) {
        int y = __shfl_up_sync(0xffffffffu, x, off);
        if (lane >= off) x += y;
    }
    if (lane == 31) warp_tot[wid] = x;
    __syncthreads();
    if (wid == 0) {
        int wt = warp_tot[lane];
        #pragma unroll
        for (int off = 1; off < 32; off <<= 1) {
            int y = __shfl_up_sync(0xffffffffu, wt, off);
            if (lane >= off) wt += y;
        }
        warp_tot[lane] = wt;
        int p = warp_sum[lane];
        #pragma unroll
        for (int off = 16; off > 0; off >>= 1)
            p += __shfl_xor_sync(0xffffffffu, p, off);
        if (lane == 0) s_prev = p;
    }
    __syncthreads();
    int wp = (wid > 0) ? warp_tot[wid - 1] : 0;
    int base = s_prev + wp + (x - tsum);

    if (act) {
        int4 rp;
        rp.x = base;
        rp.y = base + v.x;
        rp.z = base + v.x + v.y;
        rp.w = base + v.x + v.y + v.z;
        *(int4*)(g_rowptr + i) = rp;
    } else {
        int c = base;
        for (int q = 0; q < 4; q++) {
            int ii = i + q;
            if (ii < n) { g_rowptr[ii] = c; c += ((int*)&v)[q]; }
        }
    }
    if (b == gridDim.x - 1 && t == 1023)
        g_rowptr[n] = s_prev + warp_tot[31];
}

// scatter: src index only (no dinv gathers, no weight) + deferred rowcnt re-zero
__global__ void scatter_kernel(const int* __restrict__ src, const int* __restrict__ dst,
                               int e, int n) {
#if __CUDA_ARCH__ >= 900
    cudaGridDependencySynchronize();
#endif
    int i = blockIdx.x * blockDim.x + threadIdx.x;
    int i4 = i * 4;
    if (i4 + 3 < n) {
        *(int4*)(g_rowcnt + i4) = make_int4(0, 0, 0, 0);
    } else if (i4 < n) {
        for (int q = i4; q < n; q++) g_rowcnt[q] = 0;
    }
    if (i < e) {
        int d = dst[i];
        int pos = g_rowptr[d] + atomicAdd(&g_cursor[d], 1);
        g_csrs[pos] = src[i];
    }
}

// ---------------- SpMM: weightless fp16 gather, fp32 accumulate ----------------
// mode 0: Y = -dinv[row] * sum Hh[src]  -> T1 (fp32) + g_T1h (dinv*T1, fp16)
// mode 1: Y = -dinv[row] * sum T1h[src] -> T2 (fp32)
__global__ __launch_bounds__(256) void spmm_kernel(int mode, int n) {
#if __CUDA_ARCH__ >= 900
    cudaGridDependencySynchronize();
#endif
    const __half2* __restrict__ X = mode ? g_T1h : g_Hh;
    float* __restrict__ Y         = mode ? g_T2  : g_T1;
    int gid  = blockIdx.x * blockDim.x + threadIdx.x;
    int row  = gid >> 4;
    int lane = gid & 15;
    if (row >= n) return;
    int beg = g_rowptr[row], end = g_rowptr[row + 1];
    float4 a0 = make_float4(0.f, 0.f, 0.f, 0.f);
    float4 a1 = make_float4(0.f, 0.f, 0.f, 0.f);
    int e = beg;
    if ((e & 1) && e < end) {            // align to int2 boundary
        int s = g_csrs[e];
        uint2 hh = *(const uint2*)(X + s * 32 + lane * 2);
        float2 f0 = __half22float2(*(const __half2*)&hh.x);
        float2 f1 = __half22float2(*(const __half2*)&hh.y);
        a0.x += f0.x; a0.y += f0.y; a0.z += f1.x; a0.w += f1.y;
        e++;
    }
    for (; e + 2 <= end; e += 2) {
        int2 c = *(const int2*)(g_csrs + e);
        uint2 h0 = *(const uint2*)(X + c.x * 32 + lane * 2);
        uint2 h1 = *(const uint2*)(X + c.y * 32 + lane * 2);
        float2 f00 = __half22float2(*(const __half2*)&h0.x);
        float2 f01 = __half22float2(*(const __half2*)&h0.y);
        float2 f10 = __half22float2(*(const __half2*)&h1.x);
        float2 f11 = __half22float2(*(const __half2*)&h1.y);
        a0.x += f00.x; a0.y += f00.y; a0.z += f01.x; a0.w += f01.y;
        a1.x += f10.x; a1.y += f10.y; a1.z += f11.x; a1.w += f11.y;
    }
    if (e < end) {
        int s = g_csrs[e];
        uint2 hh = *(const uint2*)(X + s * 32 + lane * 2);
        float2 f0 = __half22float2(*(const __half2*)&hh.x);
        float2 f1 = __half22float2(*(const __half2*)&hh.y);
        a0.x += f0.x; a0.y += f0.y; a0.z += f1.x; a0.w += f1.y;
    }
    float dv = g_dinv[row];
    float s0 = -dv;                      // T = -dinv[d] * sum(prescaled)
    float4 r;
    r.x = s0 * (a0.x + a1.x); r.y = s0 * (a0.y + a1.y);
    r.z = s0 * (a0.z + a1.z); r.w = s0 * (a0.w + a1.w);
    *(float4*)(Y + row * HIDDIM + lane * 4) = r;
    if (!mode) {
        union { __half2 h[2]; uint2 u; } p;
        p.h[0] = __float22half2_rn(make_float2(r.x * dv, r.y * dv));
        p.h[1] = __float22half2_rn(make_float2(r.z * dv, r.w * dv));
        *(uint2*)(g_T1h + row * 32 + lane * 2) = p.u;
    }
}

// ---------------- fused layer (128 rows/block, f32x2 FMA, fused out-GEMM on last) ----
// Pass order T1, T2, H(last) so smem tile holds H at the epilogue (residual from smem).
#define LK_HT_STRIDE 129
#define LK_HT_FLOATS (64 * LK_HT_STRIDE)          // 8256
#define LK_SMEM_BYTES ((LK_HT_FLOATS + 4096) * 4) // 49408

__global__ __launch_bounds__(256) void layer_kernel(int layer,
                                                    const float* __restrict__ cb,
                                                    const float* __restrict__ lg,
                                                    const float* __restrict__ lbeta,
                                                    const float* __restrict__ Wout,
                                                    const float* __restrict__ bout,
                                                    float* __restrict__ out,
                                                    int last, int n) {
#if __CUDA_ARCH__ >= 900
    cudaGridDependencySynchronize();
#endif
    extern __shared__ float smem[];
    float* ht = smem;                 // [64][129] transposed tile
    float* sA = smem + LK_HT_FLOATS;  // [64][64] current weight matrix
    __shared__ float sWout[260];

    int t = threadIdx.x;
    int c8 = (t & 7) * 8;
    int rg = t >> 3;
    int row0 = blockIdx.x * 128;
    const float* __restrict__ A = g_A + layer * 12288;

    if (last) {
        sWout[t] = Wout[t];
        if (t < 4) sWout[256 + t] = bout[t];
    }

    unsigned long long acc[4][4];
    #pragma unroll
    for (int i = 0; i < 4; i++)
        #pragma unroll
        for (int j = 0; j < 4; j++) acc[i][j] = pack2(0.0f, 0.0f);

    #pragma unroll
    for (int pass = 0; pass < 3; pass++) {
        const float* __restrict__ S  = (pass == 0) ? g_T1 : ((pass == 1) ? g_T2 : g_H);
        const float* __restrict__ Ap = A + ((pass == 0) ? 4096 : ((pass == 1) ? 8192 : 0));
        for (int idx = t; idx < 1024; idx += 256)
            ((float4*)sA)[idx] = ((const float4*)Ap)[idx];
        for (int idx = t; idx < 2048; idx += 256) {
            int r = idx >> 4, k4 = (idx & 15) * 4;
            int grow = row0 + r;
            float4 v = make_float4(0.f, 0.f, 0.f, 0.f);
            if (grow < n) v = *(const float4*)(S + grow * 64 + k4);
            int b = k4 * LK_HT_STRIDE + r;
            ht[b]                    = v.x;
            ht[b + LK_HT_STRIDE]     = v.y;
            ht[b + 2 * LK_HT_STRIDE] = v.z;
            ht[b + 3 * LK_HT_STRIDE] = v.w;
        }
        __syncthreads();
        #pragma unroll 8
        for (int k = 0; k < 64; k++) {
            unsigned long long h2[4];
            #pragma unroll
            for (int i = 0; i < 4; i++) {
                float hv = ht[k * LK_HT_STRIDE + rg * 4 + i];
                h2[i] = pack2(hv, hv);
            }
            float4 wa = *(const float4*)&sA[k * 64 + c8];
            float4 wb = *(const float4*)&sA[k * 64 + c8 + 4];
            unsigned long long w2[4];
            w2[0] = pack2(wa.x, wa.y); w2[1] = pack2(wa.z, wa.w);
            w2[2] = pack2(wb.x, wb.y); w2[3] = pack2(wb.z, wb.w);
            #pragma unroll
            for (int i = 0; i < 4; i++)
                #pragma unroll
                for (int j = 0; j < 4; j++)
                    acc[i][j] = ffma2(h2[i], w2[j], acc[i][j]);
        }
        if (pass < 2) __syncthreads();
    }

    float cbv[8], lgv[8], lbv[8];
    {
        float4 a0 = *(const float4*)(cb + c8),    a1 = *(const float4*)(cb + c8 + 4);
        float4 g0 = *(const float4*)(lg + c8),    g1 = *(const float4*)(lg + c8 + 4);
        float4 b0 = *(const float4*)(lbeta + c8), b1 = *(const float4*)(lbeta + c8 + 4);
        cbv[0]=a0.x;cbv[1]=a0.y;cbv[2]=a0.z;cbv[3]=a0.w;cbv[4]=a1.x;cbv[5]=a1.y;cbv[6]=a1.z;cbv[7]=a1.w;
        lgv[0]=g0.x;lgv[1]=g0.y;lgv[2]=g0.z;lgv[3]=g0.w;lgv[4]=g1.x;lgv[5]=g1.y;lgv[6]=g1.z;lgv[7]=g1.w;
        lbv[0]=b0.x;lbv[1]=b0.y;lbv[2]=b0.z;lbv[3]=b0.w;lbv[4]=b1.x;lbv[5]=b1.y;lbv[6]=b1.z;lbv[7]=b1.w;
    }

    #pragma unroll
    for (int i = 0; i < 4; i++) {
        int grow = row0 + rg * 4 + i;
        float val[8];
        #pragma unroll
        for (int j = 0; j < 4; j++) {
            float2 a = unpack2(acc[i][j]);
            float hr0 = ht[(c8 + 2*j)     * LK_HT_STRIDE + rg * 4 + i];
            float hr1 = ht[(c8 + 2*j + 1) * LK_HT_STRIDE + rg * 4 + i];
            val[2*j]   = fmaxf(a.x + cbv[2*j],   0.0f) + hr0;
            val[2*j+1] = fmaxf(a.y + cbv[2*j+1], 0.0f) + hr1;
        }
        float s = 0.0f;
        #pragma unroll
        for (int u = 0; u < 8; u++) s += val[u];
        #pragma unroll
        for (int m = 1; m < 8; m <<= 1) s += __shfl_xor_sync(0xffffffffu, s, m);
        float mu = s * (1.0f / 64.0f);
        float q = 0.0f;
        #pragma unroll
        for (int u = 0; u < 8; u++) { float d = val[u] - mu; q += d * d; }
        #pragma unroll
        for (int m = 1; m < 8; m <<= 1) q += __shfl_xor_sync(0xffffffffu, q, m);
        float rs = rsqrtf(q * (1.0f / 64.0f) + LN_EPS);

        float o[8];
        #pragma unroll
        for (int u = 0; u < 8; u++)
            o[u] = (val[u] - mu) * rs * lgv[u] + lbv[u];

        if (!last) {
            if (grow < n) {
                *(float4*)(g_H + grow * 64 + c8)     = make_float4(o[0], o[1], o[2], o[3]);
                *(float4*)(g_H + grow * 64 + c8 + 4) = make_float4(o[4], o[5], o[6], o[7]);
                float dv = g_dinv[grow];
                *(uint4*)(g_Hh + grow * 32 + c8 / 2) = pack_half8s(o, dv);
            }
        } else {
            float4 oa = make_float4(0.f, 0.f, 0.f, 0.f);
            #pragma unroll
            for (int u = 0; u < 8; u++) {
                const float* wr = &sWout[(c8 + u) * 4];
                oa.x += o[u] * wr[0]; oa.y += o[u] * wr[1];
                oa.z += o[u] * wr[2]; oa.w += o[u] * wr[3];
            }
            #pragma unroll
            for (int m = 1; m < 8; m <<= 1) {
                oa.x += __shfl_xor_sync(0xffffffffu, oa.x, m);
                oa.y += __shfl_xor_sync(0xffffffffu, oa.y, m);
                oa.z += __shfl_xor_sync(0xffffffffu, oa.z, m);
                oa.w += __shfl_xor_sync(0xffffffffu, oa.w, m);
            }
            if ((t & 7) == 0 && grow < n) {
                oa.x += sWout[256]; oa.y += sWout[257]; oa.z += sWout[258]; oa.w += sWout[259];
                *(float4*)(out + grow * 4) = oa;
            }
        }
    }
}

// ---------------- PDL launch helper ----------------
template <typename F, typename... Args>
static inline void launch_pdl(F kernel, dim3 grid, dim3 block, size_t smem,
                              cudaStream_t stream, Args... args) {
    cudaLaunchConfig_t cfg = {};
    cfg.gridDim = grid; cfg.blockDim = block;
    cfg.dynamicSmemBytes = smem; cfg.stream = stream;
    cudaLaunchAttribute attr[1];
    attr[0].id = cudaLaunchAttributeProgrammaticStreamSerialization;
    attr[0].val.programmaticStreamSerializationAllowed = 1;
    cfg.attrs = attr; cfg.numAttrs = 1;
    cudaLaunchKernelEx(&cfg, kernel, args...);
}

// tiny kernel for the prepA-only branch (before dinv exists)
__global__ void prepA_kernel(const float* __restrict__ W) {
    int idx = blockIdx.x * blockDim.x + threadIdx.x;
    if (idx < 3 * 4096) {
        int i = idx >> 12, r = idx & 4095;
        const float* Wi = W + i * 3 * 4096;
        float w0 = Wi[r], w1 = Wi[4096 + r], w2 = Wi[8192 + r];
        float* Ai = g_A + i * 3 * 4096;
        Ai[r]        = w0 - w2;
        Ai[4096 + r] = w1;
        Ai[8192 + r] = 2.0f * w2;
    }
}

// ---------------- launch ----------------
extern "C" void kernel_launch(void* const* d_in, const int* in_sizes, int n_in,
                              void* d_out, int out_size) {
    const float *x = 0, *Win = 0, *bin = 0, *chW = 0, *Wout = 0, *bout = 0;
    const float *p192[3] = {0, 0, 0};
    const int* ei = 0;
    int n192 = 0, e2 = 0, nx = 0;
    for (int i = 0; i < n_in; i++) {
        int sz = in_sizes[i];
        if      (sz == 1600000) { ei = (const int*)d_in[i]; e2 = sz; }
        else if (sz == 800000)  { x = (const float*)d_in[i]; nx = sz; }
        else if (sz == 1024)    Win  = (const float*)d_in[i];
        else if (sz == 64)      bin  = (const float*)d_in[i];
        else if (sz == 36864)   chW  = (const float*)d_in[i];
        else if (sz == 256)     Wout = (const float*)d_in[i];
        else if (sz == 4)       bout = (const float*)d_in[i];
        else if (sz == 192 && n192 < 3) p192[n192++] = (const float*)d_in[i];
    }
    const float* chb = p192[0];
    const float* lng = p192[1];
    const float* lnb = p192[2];
    float* out = (float*)d_out;

    int n = nx / 16;
    int e = e2 / 2;
    const int* src = ei;
    const int* dst = ei + e;

    static cudaStream_t s1 = 0;
    static cudaEvent_t  ev0 = 0, ev_scan = 0, ev1 = 0;
    static int s_init = 0;
    if (!s_init) {
        cudaStreamCreateWithFlags(&s1, cudaStreamNonBlocking);
        cudaEventCreateWithFlags(&ev0, cudaEventDisableTiming);
        cudaEventCreateWithFlags(&ev_scan, cudaEventDisableTiming);
        cudaEventCreateWithFlags(&ev1, cudaEventDisableTiming);
        cudaFuncSetAttribute(layer_kernel, cudaFuncAttributeMaxDynamicSharedMemorySize,
                             LK_SMEM_BYTES);
        s_init = 1;
    }

    cudaStream_t s0 = 0;
    int gemm_blocks   = (n + 31) / 32;
    int layer_blocks  = (n + 127) / 128;
    int spmm_blocks   = (n * 16 + 255) / 256;
    int scan_blocks   = (n + SCAN_CHUNK - 1) / SCAN_CHUNK;

    // fork: prepA immediately on s1 (no deps)
    cudaEventRecord(ev0, s0);
    cudaStreamWaitEvent(s1, ev0, 0);
    prepA_kernel<<<48, 256, 0, s1>>>(chW);

    // CSR build on s0 with PDL between dependent nodes
    count_kernel<<<(e + 255) / 256, 256, 0, s0>>>(src, dst, e);
    launch_pdl(scan_kernel, dim3(scan_blocks), dim3(1024), 0, s0, n);
    cudaEventRecord(ev_scan, s0);                 // dinv ready
    launch_pdl(scatter_kernel, dim3((e + 255) / 256), dim3(256), 0, s0, src, dst, e, n);

    // ingemm (needs dinv) on s1, concurrent with scatter
    cudaStreamWaitEvent(s1, ev_scan, 0);
    ingemm_prep_kernel<<<gemm_blocks, 256, 0, s1>>>(x, Win, bin, chW, gemm_blocks, n);
    cudaEventRecord(ev1, s1);
    cudaStreamWaitEvent(s0, ev1, 0);

    for (int i = 0; i < 3; i++) {
        if (i == 0) {
            spmm_kernel<<<spmm_blocks, 256, 0, s0>>>(0, n);
        } else {
            launch_pdl(spmm_kernel, dim3(spmm_blocks), dim3(256), 0, s0, 0, n);
        }
        launch_pdl(spmm_kernel, dim3(spmm_blocks), dim3(256), 0, s0, 1, n);
        launch_pdl(layer_kernel, dim3(layer_blocks), dim3(256), (size_t)LK_SMEM_BYTES, s0,
                   i, chb + i * 64, lng + i * 64, lnb + i * 64,
                   Wout, bout, out, (i == 2) ? 1 : 0, n);
    }
}

// round 15
// speedup vs baseline: 1.5824x; 1.5824x over previous
#include <cuda_runtime.h>
#include <cuda_fp16.h>

#define NMAX 50000
#define EMAX 800000
#define HIDDIM 64
#define LN_EPS 1e-5f
#define SCAN_CHUNK 4096

// ---------------- scratch (device globals; no allocation allowed) ----------------
// Self-cleaning counters: zero at module load; scan_kernel zeroes srcdeg/cursor
// (own chunk), scatter_kernel zeroes rowcnt. Deterministic across graph replays.
// fp16 feature arrays are PRE-SCALED by dinv: g_Hh = dinv*H, g_T1h = dinv*T1,
// so CSR entries need no weight (w*H[s] = -dinv[d] * (dinv[s]*H[s])).
__device__ __align__(16) int   g_srcdeg[NMAX];
__device__ __align__(16) int   g_rowcnt[NMAX];
__device__ __align__(16) int   g_cursor[NMAX];
__device__ __align__(16) int   g_rowptr[NMAX + 1];
__device__ __align__(16) float g_dinv[NMAX];
__device__ __align__(16) int   g_csrs[EMAX];             // src index only, grouped by dst
__device__ __align__(16) float g_H [NMAX * HIDDIM];
__device__ __align__(16) float g_T1[NMAX * HIDDIM];
__device__ __align__(16) float g_T2[NMAX * HIDDIM];
__device__ __align__(16) __half2 g_Hh [NMAX * 32];       // fp16 dinv*H  (spmm gather)
__device__ __align__(16) __half2 g_T1h[NMAX * 32];       // fp16 dinv*T1 (spmm gather)
__device__ __align__(16) float g_A [3 * 3 * HIDDIM * HIDDIM];  // folded weights per layer

// ---------------- f32x2 packed-FMA helpers (sm_100+ PTX) ----------------
__device__ __forceinline__ unsigned long long pack2(float a, float b) {
    unsigned long long r;
    asm("mov.b64 %0, {%1, %2};" : "=l"(r) : "f"(a), "f"(b));
    return r;
}
__device__ __forceinline__ unsigned long long ffma2(unsigned long long a,
                                                    unsigned long long b,
                                                    unsigned long long c) {
    unsigned long long d;
    asm("fma.rn.f32x2 %0, %1, %2, %3;" : "=l"(d) : "l"(a), "l"(b), "l"(c));
    return d;
}
__device__ __forceinline__ float2 unpack2(unsigned long long v) {
    float2 f;
    asm("mov.b64 {%0, %1}, %2;" : "=f"(f.x), "=f"(f.y) : "l"(v));
    return f;
}

// pack 8 floats (scaled by s) -> uint4 of 8 halves
__device__ __forceinline__ uint4 pack_half8s(const float* o, float s) {
    union { __half2 h[4]; uint4 u; } p;
    p.h[0] = __float22half2_rn(make_float2(o[0] * s, o[1] * s));
    p.h[1] = __float22half2_rn(make_float2(o[2] * s, o[3] * s));
    p.h[2] = __float22half2_rn(make_float2(o[4] * s, o[5] * s));
    p.h[3] = __float22half2_rn(make_float2(o[6] * s, o[7] * s));
    return p.u;
}

// ---------------- fused input GEMM + weight folding ----------------
// NOTE: runs AFTER scan (needs dinv for the pre-scaled g_Hh store).
__global__ __launch_bounds__(256) void ingemm_prep_kernel(const float* __restrict__ x,
                                                          const float* __restrict__ Win,
                                                          const float* __restrict__ bin,
                                                          const float* __restrict__ chW,
                                                          int gemm_blocks, int n) {
    if (blockIdx.x >= gemm_blocks) {
        int idx = (blockIdx.x - gemm_blocks) * 256 + threadIdx.x;
        if (idx < 3 * 4096) {
            int i = idx >> 12, r = idx & 4095;
            const float* Wi = chW + i * 3 * 4096;
            float w0 = Wi[r], w1 = Wi[4096 + r], w2 = Wi[8192 + r];
            float* Ai = g_A + i * 3 * 4096;
            Ai[r]        = w0 - w2;
            Ai[4096 + r] = w1;
            Ai[8192 + r] = 2.0f * w2;
        }
        return;
    }
    __shared__ float sW[16 * 64];
    __shared__ float xt[16 * 33];
    __shared__ float so[32 * 65];
    int t = threadIdx.x, lane = t & 31, wg = t >> 5;
    int row0 = blockIdx.x * 32;
    for (int idx = t; idx < 1024; idx += 256) sW[idx] = Win[idx];
    for (int idx = t; idx < 512; idx += 256) {
        int r = idx >> 4, k = idx & 15;
        int row = row0 + r;
        xt[k * 33 + r] = (row < n) ? x[row * 16 + k] : 0.0f;
    }
    __syncthreads();
    float acc[8] = {0, 0, 0, 0, 0, 0, 0, 0};
    #pragma unroll
    for (int k = 0; k < 16; k++) {
        float xv = xt[k * 33 + lane];
        float4 w0 = *(const float4*)&sW[k * 64 + wg * 8];
        float4 w1 = *(const float4*)&sW[k * 64 + wg * 8 + 4];
        acc[0] += xv * w0.x; acc[1] += xv * w0.y; acc[2] += xv * w0.z; acc[3] += xv * w0.w;
        acc[4] += xv * w1.x; acc[5] += xv * w1.y; acc[6] += xv * w1.z; acc[7] += xv * w1.w;
    }
    #pragma unroll
    for (int u = 0; u < 8; u++) {
        int j = wg * 8 + u;
        so[lane * 65 + j] = acc[u] + bin[j];
    }
    __syncthreads();
    int r = t >> 3, c = (t & 7) * 8;
    int row = row0 + r;
    if (row < n) {
        float v[8];
        #pragma unroll
        for (int u = 0; u < 8; u++) v[u] = so[r * 65 + c + u];
        *(float4*)(g_H + row * 64 + c)     = make_float4(v[0], v[1], v[2], v[3]);
        *(float4*)(g_H + row * 64 + c + 4) = make_float4(v[4], v[5], v[6], v[7]);
        float dv = g_dinv[row];
        *(uint4*)(g_Hh + row * 32 + c / 2) = pack_half8s(v, dv);
    }
}

// scalar, 1 edge/thread (measured fastest across rounds)
__global__ void count_kernel(const int* __restrict__ src, const int* __restrict__ dst, int e) {
    int i = blockIdx.x * blockDim.x + threadIdx.x;
    if (i < e) {
        atomicAdd(&g_srcdeg[src[i]], 1);
        atomicAdd(&g_rowcnt[dst[i]], 1);
    }
}

// ---------------- communication-free scan: rowcnt -> rowptr (exclusive) --------
__global__ __launch_bounds__(1024) void scan_kernel(int n) {
#if __CUDA_ARCH__ >= 900
    cudaGridDependencySynchronize();
#endif
    __shared__ int warp_tot[32];
    __shared__ int warp_sum[32];
    __shared__ int s_prev;
    int b = blockIdx.x, t = threadIdx.x, lane = t & 31, wid = t >> 5;
    int i = b * SCAN_CHUNK + t * 4;
    const int4 zero4 = make_int4(0, 0, 0, 0);

    int4 v = zero4;
    bool act = (i + 3) < n;
    if (act) {
        v = *(const int4*)(g_rowcnt + i);
        int4 dg = *(const int4*)(g_srcdeg + i);
        *(int4*)(g_srcdeg + i) = zero4;
        *(int4*)(g_cursor + i) = zero4;
        float4 dv;
        dv.x = (dg.x > 0) ? rsqrtf((float)dg.x) : 0.0f;
        dv.y = (dg.y > 0) ? rsqrtf((float)dg.y) : 0.0f;
        dv.z = (dg.z > 0) ? rsqrtf((float)dg.z) : 0.0f;
        dv.w = (dg.w > 0) ? rsqrtf((float)dg.w) : 0.0f;
        *(float4*)(g_dinv + i) = dv;
    } else {
        for (int q = 0; q < 4; q++) {
            int ii = i + q;
            if (ii < n) {
                ((int*)&v)[q] = g_rowcnt[ii];
                int d = g_srcdeg[ii]; g_srcdeg[ii] = 0;
                g_cursor[ii] = 0;
                g_dinv[ii] = (d > 0) ? rsqrtf((float)d) : 0.0f;
            }
        }
    }

    int psum = 0;
    int m = b * SCAN_CHUNK;
    for (int j = t * 4; j < m; j += 4096) {
        int4 c = *(const int4*)(g_rowcnt + j);
        psum += c.x + c.y + c.z + c.w;
    }
    #pragma unroll
    for (int off = 16; off > 0; off >>= 1)
        psum += __shfl_xor_sync(0xffffffffu, psum, off);
    if (lane == 0) warp_sum[wid] = psum;

    int tsum = v.x + v.y + v.z + v.w;
    int x = tsum;
    #pragma unroll
    for (int off = 1; off < 32; off <<= 1) {
        int y = __shfl_up_sync(0xffffffffu, x, off);
        if (lane >= off) x += y;
    }
    if (lane == 31) warp_tot[wid] = x;
    __syncthreads();
    if (wid == 0) {
        int wt = warp_tot[lane];
        #pragma unroll
        for (int off = 1; off < 32; off <<= 1) {
            int y = __shfl_up_sync(0xffffffffu, wt, off);
            if (lane >= off) wt += y;
        }
        warp_tot[lane] = wt;
        int p = warp_sum[lane];
        #pragma unroll
        for (int off = 16; off > 0; off >>= 1)
            p += __shfl_xor_sync(0xffffffffu, p, off);
        if (lane == 0) s_prev = p;
    }
    __syncthreads();
    int wp = (wid > 0) ? warp_tot[wid - 1] : 0;
    int base = s_prev + wp + (x - tsum);

    if (act) {
        int4 rp;
        rp.x = base;
        rp.y = base + v.x;
        rp.z = base + v.x + v.y;
        rp.w = base + v.x + v.y + v.z;
        *(int4*)(g_rowptr + i) = rp;
    } else {
        int c = base;
        for (int q = 0; q < 4; q++) {
            int ii = i + q;
            if (ii < n) { g_rowptr[ii] = c; c += ((int*)&v)[q]; }
        }
    }
    if (b == gridDim.x - 1 && t == 1023)
        g_rowptr[n] = s_prev + warp_tot[31];
}

// scatter: src index only (no dinv gathers, no weight) + deferred rowcnt re-zero
__global__ void scatter_kernel(const int* __restrict__ src, const int* __restrict__ dst,
                               int e, int n) {
#if __CUDA_ARCH__ >= 900
    cudaGridDependencySynchronize();
#endif
    int i = blockIdx.x * blockDim.x + threadIdx.x;
    int i4 = i * 4;
    if (i4 + 3 < n) {
        *(int4*)(g_rowcnt + i4) = make_int4(0, 0, 0, 0);
    } else if (i4 < n) {
        for (int q = i4; q < n; q++) g_rowcnt[q] = 0;
    }
    if (i < e) {
        int d = dst[i];
        int pos = g_rowptr[d] + atomicAdd(&g_cursor[d], 1);
        g_csrs[pos] = src[i];
    }
}

// ---------------- SpMM: weightless fp16 gather, fp32 accumulate ----------------
// mode 0: Y = -dinv[row] * sum Hh[src]  -> T1 (fp32) + g_T1h (dinv*T1, fp16)
// mode 1: Y = -dinv[row] * sum T1h[src] -> T2 (fp32)
__global__ __launch_bounds__(256) void spmm_kernel(int mode, int n) {
#if __CUDA_ARCH__ >= 900
    cudaGridDependencySynchronize();
#endif
    const __half2* __restrict__ X = mode ? g_T1h : g_Hh;
    float* __restrict__ Y         = mode ? g_T2  : g_T1;
    int gid  = blockIdx.x * blockDim.x + threadIdx.x;
    int row  = gid >> 4;
    int lane = gid & 15;
    if (row >= n) return;
    int beg = g_rowptr[row], end = g_rowptr[row + 1];
    float4 a0 = make_float4(0.f, 0.f, 0.f, 0.f);
    float4 a1 = make_float4(0.f, 0.f, 0.f, 0.f);
    int e = beg;
    if ((e & 1) && e < end) {            // align to int2 boundary
        int s = g_csrs[e];
        uint2 hh = *(const uint2*)(X + s * 32 + lane * 2);
        float2 f0 = __half22float2(*(const __half2*)&hh.x);
        float2 f1 = __half22float2(*(const __half2*)&hh.y);
        a0.x += f0.x; a0.y += f0.y; a0.z += f1.x; a0.w += f1.y;
        e++;
    }
    for (; e + 2 <= end; e += 2) {
        int2 c = *(const int2*)(g_csrs + e);
        uint2 h0 = *(const uint2*)(X + c.x * 32 + lane * 2);
        uint2 h1 = *(const uint2*)(X + c.y * 32 + lane * 2);
        float2 f00 = __half22float2(*(const __half2*)&h0.x);
        float2 f01 = __half22float2(*(const __half2*)&h0.y);
        float2 f10 = __half22float2(*(const __half2*)&h1.x);
        float2 f11 = __half22float2(*(const __half2*)&h1.y);
        a0.x += f00.x; a0.y += f00.y; a0.z += f01.x; a0.w += f01.y;
        a1.x += f10.x; a1.y += f10.y; a1.z += f11.x; a1.w += f11.y;
    }
    if (e < end) {
        int s = g_csrs[e];
        uint2 hh = *(const uint2*)(X + s * 32 + lane * 2);
        float2 f0 = __half22float2(*(const __half2*)&hh.x);
        float2 f1 = __half22float2(*(const __half2*)&hh.y);
        a0.x += f0.x; a0.y += f0.y; a0.z += f1.x; a0.w += f1.y;
    }
    float dv = g_dinv[row];
    float s0 = -dv;                      // T = -dinv[d] * sum(prescaled)
    float4 r;
    r.x = s0 * (a0.x + a1.x); r.y = s0 * (a0.y + a1.y);
    r.z = s0 * (a0.z + a1.z); r.w = s0 * (a0.w + a1.w);
    *(float4*)(Y + row * HIDDIM + lane * 4) = r;
    if (!mode) {
        union { __half2 h[2]; uint2 u; } p;
        p.h[0] = __float22half2_rn(make_float2(r.x * dv, r.y * dv));
        p.h[1] = __float22half2_rn(make_float2(r.z * dv, r.w * dv));
        *(uint2*)(g_T1h + row * 32 + lane * 2) = p.u;
    }
}

// ---------------- fused layer (128 rows/block, f32x2 FMA, fused out-GEMM on last) ----
// Pass order T1, T2, H(last) so smem tile holds H at the epilogue (residual from smem).
#define LK_HT_STRIDE 129
#define LK_HT_FLOATS (64 * LK_HT_STRIDE)          // 8256
#define LK_SMEM_BYTES ((LK_HT_FLOATS + 4096) * 4) // 49408

__global__ __launch_bounds__(256) void layer_kernel(int layer,
                                                    const float* __restrict__ cb,
                                                    const float* __restrict__ lg,
                                                    const float* __restrict__ lbeta,
                                                    const float* __restrict__ Wout,
                                                    const float* __restrict__ bout,
                                                    float* __restrict__ out,
                                                    int last, int n) {
#if __CUDA_ARCH__ >= 900
    cudaGridDependencySynchronize();
#endif
    extern __shared__ float smem[];
    float* ht = smem;                 // [64][129] transposed tile
    float* sA = smem + LK_HT_FLOATS;  // [64][64] current weight matrix
    __shared__ float sWout[260];

    int t = threadIdx.x;
    int c8 = (t & 7) * 8;
    int rg = t >> 3;
    int row0 = blockIdx.x * 128;
    const float* __restrict__ A = g_A + layer * 12288;

    if (last) {
        sWout[t] = Wout[t];
        if (t < 4) sWout[256 + t] = bout[t];
    }

    unsigned long long acc[4][4];
    #pragma unroll
    for (int i = 0; i < 4; i++)
        #pragma unroll
        for (int j = 0; j < 4; j++) acc[i][j] = pack2(0.0f, 0.0f);

    #pragma unroll
    for (int pass = 0; pass < 3; pass++) {
        const float* __restrict__ S  = (pass == 0) ? g_T1 : ((pass == 1) ? g_T2 : g_H);
        const float* __restrict__ Ap = A + ((pass == 0) ? 4096 : ((pass == 1) ? 8192 : 0));
        for (int idx = t; idx < 1024; idx += 256)
            ((float4*)sA)[idx] = ((const float4*)Ap)[idx];
        for (int idx = t; idx < 2048; idx += 256) {
            int r = idx >> 4, k4 = (idx & 15) * 4;
            int grow = row0 + r;
            float4 v = make_float4(0.f, 0.f, 0.f, 0.f);
            if (grow < n) v = *(const float4*)(S + grow * 64 + k4);
            int b = k4 * LK_HT_STRIDE + r;
            ht[b]                    = v.x;
            ht[b + LK_HT_STRIDE]     = v.y;
            ht[b + 2 * LK_HT_STRIDE] = v.z;
            ht[b + 3 * LK_HT_STRIDE] = v.w;
        }
        __syncthreads();
        #pragma unroll 8
        for (int k = 0; k < 64; k++) {
            unsigned long long h2[4];
            #pragma unroll
            for (int i = 0; i < 4; i++) {
                float hv = ht[k * LK_HT_STRIDE + rg * 4 + i];
                h2[i] = pack2(hv, hv);
            }
            float4 wa = *(const float4*)&sA[k * 64 + c8];
            float4 wb = *(const float4*)&sA[k * 64 + c8 + 4];
            unsigned long long w2[4];
            w2[0] = pack2(wa.x, wa.y); w2[1] = pack2(wa.z, wa.w);
            w2[2] = pack2(wb.x, wb.y); w2[3] = pack2(wb.z, wb.w);
            #pragma unroll
            for (int i = 0; i < 4; i++)
                #pragma unroll
                for (int j = 0; j < 4; j++)
                    acc[i][j] = ffma2(h2[i], w2[j], acc[i][j]);
        }
        if (pass < 2) __syncthreads();
    }

    float cbv[8], lgv[8], lbv[8];
    {
        float4 a0 = *(const float4*)(cb + c8),    a1 = *(const float4*)(cb + c8 + 4);
        float4 g0 = *(const float4*)(lg + c8),    g1 = *(const float4*)(lg + c8 + 4);
        float4 b0 = *(const float4*)(lbeta + c8), b1 = *(const float4*)(lbeta + c8 + 4);
        cbv[0]=a0.x;cbv[1]=a0.y;cbv[2]=a0.z;cbv[3]=a0.w;cbv[4]=a1.x;cbv[5]=a1.y;cbv[6]=a1.z;cbv[7]=a1.w;
        lgv[0]=g0.x;lgv[1]=g0.y;lgv[2]=g0.z;lgv[3]=g0.w;lgv[4]=g1.x;lgv[5]=g1.y;lgv[6]=g1.z;lgv[7]=g1.w;
        lbv[0]=b0.x;lbv[1]=b0.y;lbv[2]=b0.z;lbv[3]=b0.w;lbv[4]=b1.x;lbv[5]=b1.y;lbv[6]=b1.z;lbv[7]=b1.w;
    }

    #pragma unroll
    for (int i = 0; i < 4; i++) {
        int grow = row0 + rg * 4 + i;
        float val[8];
        #pragma unroll
        for (int j = 0; j < 4; j++) {
            float2 a = unpack2(acc[i][j]);
            float hr0 = ht[(c8 + 2*j)     * LK_HT_STRIDE + rg * 4 + i];
            float hr1 = ht[(c8 + 2*j + 1) * LK_HT_STRIDE + rg * 4 + i];
            val[2*j]   = fmaxf(a.x + cbv[2*j],   0.0f) + hr0;
            val[2*j+1] = fmaxf(a.y + cbv[2*j+1], 0.0f) + hr1;
        }
        float s = 0.0f;
        #pragma unroll
        for (int u = 0; u < 8; u++) s += val[u];
        #pragma unroll
        for (int m = 1; m < 8; m <<= 1) s += __shfl_xor_sync(0xffffffffu, s, m);
        float mu = s * (1.0f / 64.0f);
        float q = 0.0f;
        #pragma unroll
        for (int u = 0; u < 8; u++) { float d = val[u] - mu; q += d * d; }
        #pragma unroll
        for (int m = 1; m < 8; m <<= 1) q += __shfl_xor_sync(0xffffffffu, q, m);
        float rs = rsqrtf(q * (1.0f / 64.0f) + LN_EPS);

        float o[8];
        #pragma unroll
        for (int u = 0; u < 8; u++)
            o[u] = (val[u] - mu) * rs * lgv[u] + lbv[u];

        if (!last) {
            if (grow < n) {
                *(float4*)(g_H + grow * 64 + c8)     = make_float4(o[0], o[1], o[2], o[3]);
                *(float4*)(g_H + grow * 64 + c8 + 4) = make_float4(o[4], o[5], o[6], o[7]);
                float dv = g_dinv[grow];
                *(uint4*)(g_Hh + grow * 32 + c8 / 2) = pack_half8s(o, dv);
            }
        } else {
            float4 oa = make_float4(0.f, 0.f, 0.f, 0.f);
            #pragma unroll
            for (int u = 0; u < 8; u++) {
                const float* wr = &sWout[(c8 + u) * 4];
                oa.x += o[u] * wr[0]; oa.y += o[u] * wr[1];
                oa.z += o[u] * wr[2]; oa.w += o[u] * wr[3];
            }
            #pragma unroll
            for (int m = 1; m < 8; m <<= 1) {
                oa.x += __shfl_xor_sync(0xffffffffu, oa.x, m);
                oa.y += __shfl_xor_sync(0xffffffffu, oa.y, m);
                oa.z += __shfl_xor_sync(0xffffffffu, oa.z, m);
                oa.w += __shfl_xor_sync(0xffffffffu, oa.w, m);
            }
            if ((t & 7) == 0 && grow < n) {
                oa.x += sWout[256]; oa.y += sWout[257]; oa.z += sWout[258]; oa.w += sWout[259];
                *(float4*)(out + grow * 4) = oa;
            }
        }
    }
}

// ---------------- PDL launch helper ----------------
template <typename F, typename... Args>
static inline void launch_pdl(F kernel, dim3 grid, dim3 block, size_t smem,
                              cudaStream_t stream, Args... args) {
    cudaLaunchConfig_t cfg = {};
    cfg.gridDim = grid; cfg.blockDim = block;
    cfg.dynamicSmemBytes = smem; cfg.stream = stream;
    cudaLaunchAttribute attr[1];
    attr[0].id = cudaLaunchAttributeProgrammaticStreamSerialization;
    attr[0].val.programmaticStreamSerializationAllowed = 1;
    cfg.attrs = attr; cfg.numAttrs = 1;
    cudaLaunchKernelEx(&cfg, kernel, args...);
}

// tiny kernel for the prepA-only branch (before dinv exists)
__global__ void prepA_kernel(const float* __restrict__ W) {
    int idx = blockIdx.x * blockDim.x + threadIdx.x;
    if (idx < 3 * 4096) {
        int i = idx >> 12, r = idx & 4095;
        const float* Wi = W + i * 3 * 4096;
        float w0 = Wi[r], w1 = Wi[4096 + r], w2 = Wi[8192 + r];
        float* Ai = g_A + i * 3 * 4096;
        Ai[r]        = w0 - w2;
        Ai[4096 + r] = w1;
        Ai[8192 + r] = 2.0f * w2;
    }
}

// ---------------- launch ----------------
extern "C" void kernel_launch(void* const* d_in, const int* in_sizes, int n_in,
                              void* d_out, int out_size) {
    const float *x = 0, *Win = 0, *bin = 0, *chW = 0, *Wout = 0, *bout = 0;
    const float *p192[3] = {0, 0, 0};
    const int* ei = 0;
    int n192 = 0, e2 = 0, nx = 0;
    for (int i = 0; i < n_in; i++) {
        int sz = in_sizes[i];
        if      (sz == 1600000) { ei = (const int*)d_in[i]; e2 = sz; }
        else if (sz == 800000)  { x = (const float*)d_in[i]; nx = sz; }
        else if (sz == 1024)    Win  = (const float*)d_in[i];
        else if (sz == 64)      bin  = (const float*)d_in[i];
        else if (sz == 36864)   chW  = (const float*)d_in[i];
        else if (sz == 256)     Wout = (const float*)d_in[i];
        else if (sz == 4)       bout = (const float*)d_in[i];
        else if (sz == 192 && n192 < 3) p192[n192++] = (const float*)d_in[i];
    }
    const float* chb = p192[0];
    const float* lng = p192[1];
    const float* lnb = p192[2];
    float* out = (float*)d_out;

    int n = nx / 16;
    int e = e2 / 2;
    const int* src = ei;
    const int* dst = ei + e;

    static cudaStream_t s1 = 0;
    static cudaEvent_t  ev0 = 0, ev_scan = 0, ev1 = 0;
    static int s_init = 0;
    if (!s_init) {
        cudaStreamCreateWithFlags(&s1, cudaStreamNonBlocking);
        cudaEventCreateWithFlags(&ev0, cudaEventDisableTiming);
        cudaEventCreateWithFlags(&ev_scan, cudaEventDisableTiming);
        cudaEventCreateWithFlags(&ev1, cudaEventDisableTiming);
        cudaFuncSetAttribute(layer_kernel, cudaFuncAttributeMaxDynamicSharedMemorySize,
                             LK_SMEM_BYTES);
        s_init = 1;
    }

    cudaStream_t s0 = 0;
    int gemm_blocks   = (n + 31) / 32;
    int layer_blocks  = (n + 127) / 128;
    int spmm_blocks   = (n * 16 + 255) / 256;
    int scan_blocks   = (n + SCAN_CHUNK - 1) / SCAN_CHUNK;

    // fork: prepA immediately on s1 (no deps)
    cudaEventRecord(ev0, s0);
    cudaStreamWaitEvent(s1, ev0, 0);
    prepA_kernel<<<48, 256, 0, s1>>>(chW);

    // CSR build on s0 with PDL between dependent nodes
    count_kernel<<<(e + 255) / 256, 256, 0, s0>>>(src, dst, e);
    launch_pdl(scan_kernel, dim3(scan_blocks), dim3(1024), 0, s0, n);
    cudaEventRecord(ev_scan, s0);                 // dinv ready
    launch_pdl(scatter_kernel, dim3((e + 255) / 256), dim3(256), 0, s0, src, dst, e, n);

    // ingemm (needs dinv) on s1, concurrent with scatter
    cudaStreamWaitEvent(s1, ev_scan, 0);
    ingemm_prep_kernel<<<gemm_blocks, 256, 0, s1>>>(x, Win, bin, chW, gemm_blocks, n);
    cudaEventRecord(ev1, s1);
    cudaStreamWaitEvent(s0, ev1, 0);

    for (int i = 0; i < 3; i++) {
        if (i == 0) {
            spmm_kernel<<<spmm_blocks, 256, 0, s0>>>(0, n);
        } else {
            launch_pdl(spmm_kernel, dim3(spmm_blocks), dim3(256), 0, s0, 0, n);
        }
        launch_pdl(spmm_kernel, dim3(spmm_blocks), dim3(256), 0, s0, 1, n);
        launch_pdl(layer_kernel, dim3(layer_blocks), dim3(256), (size_t)LK_SMEM_BYTES, s0,
                   i, chb + i * 64, lng + i * 64, lnb + i * 64,
                   Wout, bout, out, (i == 2) ? 1 : 0, n);
    }
}